// round 3
// baseline (speedup 1.0000x reference)
#include <cuda_runtime.h>
#include <cuda_bf16.h>
#include <cstdint>

// ExpandHarmonics. Output (float32): [hkl 3M | dHKL M | wav M | meta DM*M].
// R3: float4-vectorized meta copy + fused scalar outputs, streaming stores.

#define MAXN   (1 << 20)
#define BLK    256
#define MAXB   ((MAXN + BLK - 1) / BLK)
#define MAXM   (1 << 23)

__device__ int           g_rowoff[MAXN];
__device__ unsigned char g_cnt[MAXN];
__device__ int           g_blocksum[MAXB + 1];
__device__ int           g_pack[MAXM];       // (src_idx << 8) | harmonic_n
__device__ unsigned int  g_hkl0[MAXN];       // h0 | k0<<8 | l0<<16
__device__ float         g_d0[MAXN];         // dHKL * g
__device__ float         g_w0[MAXN];         // wavelength * g

__device__ __forceinline__ int gcd2(int a, int b) {
    while (b) { int t = a % b; a = b; b = t; }
    return a;
}

// ---- Pass 1: per-row count + precompute + in-block scan ----
__global__ __launch_bounds__(BLK)
void k_count(const int* __restrict__ hkl, const float* __restrict__ dHKL,
             const float* __restrict__ wav, const float* __restrict__ dmin, int N) {
    __shared__ int s[BLK];
    int i = blockIdx.x * BLK + threadIdx.x;
    int cnt = 0;
    if (i < N) {
        int h = hkl[3 * i], k = hkl[3 * i + 1], l = hkl[3 * i + 2];
        int g = gcd2(gcd2(h, k), l);
        float fg = (float)g;
        float d0 = dHKL[i] * fg;
        cnt = (int)floorf(d0 / dmin[0]);
        g_hkl0[i] = (unsigned)(h / g) | ((unsigned)(k / g) << 8) | ((unsigned)(l / g) << 16);
        g_d0[i] = d0;
        g_w0[i] = wav[i] * fg;
    }
    s[threadIdx.x] = cnt;
    __syncthreads();
    #pragma unroll
    for (int off = 1; off < BLK; off <<= 1) {
        int t = (threadIdx.x >= off) ? s[threadIdx.x - off] : 0;
        __syncthreads();
        s[threadIdx.x] += t;
        __syncthreads();
    }
    if (i < N) {
        g_rowoff[i] = s[threadIdx.x] - cnt;
        g_cnt[i]    = (unsigned char)cnt;
    }
    if (threadIdx.x == 0) g_blocksum[blockIdx.x] = s[BLK - 1];
}

// ---- Pass 2: single-block exclusive scan of block sums ----
__global__ __launch_bounds__(1024)
void k_scan_blocks(int B) {
    __shared__ int s[1024];
    int tid = threadIdx.x;
    int ipt = (B + 1023) / 1024;
    int local[8];
    int start = tid * ipt;
    int sum = 0;
    for (int j = 0; j < ipt; j++) {
        int idx = start + j;
        int v = (idx < B) ? g_blocksum[idx] : 0;
        local[j] = sum;
        sum += v;
    }
    s[tid] = sum;
    __syncthreads();
    #pragma unroll
    for (int off = 1; off < 1024; off <<= 1) {
        int t = (tid >= off) ? s[tid - off] : 0;
        __syncthreads();
        s[tid] += t;
        __syncthreads();
    }
    int base = s[tid] - sum;
    for (int j = 0; j < ipt; j++) {
        int idx = start + j;
        if (idx < B) g_blocksum[idx] = base + local[j];
    }
    if (tid == 1023) g_blocksum[B] = s[1023];
}

// ---- Pass 3: per-output-row (idx, n) pack ----
__global__ __launch_bounds__(BLK)
void k_pack(int N) {
    int i = blockIdx.x * BLK + threadIdx.x;
    if (i >= N) return;
    int off = g_rowoff[i] + g_blocksum[blockIdx.x];
    int cnt = g_cnt[i];
    int tag = i << 8;
    for (int n = 1; n <= cnt; n++)
        g_pack[off + n - 1] = tag | n;
}

// ---- Fused scatter: 4 output rows per warp. Meta copy (float4 or scalar) +
//      scalar outputs on lanes 0..19 (5 per row). ----
template<bool VEC4>
__global__ __launch_bounds__(256)
void k_scatter(const float* __restrict__ meta, float* __restrict__ out, int M, int DM) {
    int gw   = (blockIdx.x * 256 + threadIdx.x) >> 5;
    int lane = threadIdx.x & 31;
    int r = lane >> 3;          // row slot within warp (0..3)
    int c = lane & 7;           // lane within row (0..7)
    int m = gw * 4 + r;

    int pack = 0;
    if (m < M) pack = g_pack[m];

    // ---- meta copy ----
    if (m < M) {
        int idx = pack >> 8;
        if (VEC4) {
            const float4* src = (const float4*)(meta + (size_t)idx * DM);
            float4*       dst = (float4*)(out + (size_t)5 * M + (size_t)m * DM);
            int DM4 = DM >> 2;
            for (int e = c; e < DM4; e += 8)
                __stcs(&dst[e], src[e]);
        } else {
            const float* src = meta + (size_t)idx * DM;
            float*       dst = out + (size_t)5 * M + (size_t)m * DM;
            for (int e = c; e < DM; e += 8)
                __stcs(&dst[e], src[e]);
        }
    }

    // ---- scalar outputs: lanes 0..19, lane = rr*5 + j ----
    int rr = lane / 5;
    int j  = lane - rr * 5;
    // all lanes participate in the shuffle; source lane rr*8 holds pack for row gw*4+rr
    int p2 = __shfl_sync(0xffffffffu, pack, (lane < 20 ? rr : 0) * 8);
    if (lane < 20) {
        int m2 = gw * 4 + rr;
        if (m2 < M) {
            int idx2 = p2 >> 8;
            int n    = p2 & 255;
            if (j < 3) {
                unsigned hp = g_hkl0[idx2];
                int comp = (int)((hp >> (8 * j)) & 255u);
                __stcs(&out[3 * m2 + j], (float)(comp * n));
            } else if (j == 3) {
                __stcs(&out[3 * M + m2], g_d0[idx2] / (float)n);
            } else {
                __stcs(&out[4 * M + m2], g_w0[idx2] / (float)n);
            }
        }
    }
}

extern "C" void kernel_launch(void* const* d_in, const int* in_sizes, int n_in,
                              void* d_out, int out_size) {
    const int*   hkl  = (const int*)  d_in[0];
    const float* dHKL = (const float*)d_in[1];
    const float* wav  = (const float*)d_in[2];
    const float* meta = (const float*)d_in[3];
    const float* dmin = (const float*)d_in[4];

    int N  = in_sizes[1];
    int DM = in_sizes[3] / N;
    int M  = out_size / (5 + DM);

    int B = (N + BLK - 1) / BLK;

    k_count<<<B, BLK>>>(hkl, dHKL, wav, dmin, N);
    k_scan_blocks<<<1, 1024>>>(B);
    k_pack<<<B, BLK>>>(N);

    int rowsPerBlock = 8 * 4;  // 8 warps * 4 rows
    int grid = (M + rowsPerBlock - 1) / rowsPerBlock;
    // float4 path requires: DM%4==0 and the meta destination base (5*M floats) 16B-aligned
    bool vec = ((DM & 3) == 0) && (((5 * (size_t)M) & 3) == 0);
    if (vec)
        k_scatter<true><<<grid, 256>>>(meta, (float*)d_out, M, DM);
    else
        k_scatter<false><<<grid, 256>>>(meta, (float*)d_out, M, DM);
}

// round 4
// speedup vs baseline: 1.1512x; 1.1512x over previous
#include <cuda_runtime.h>
#include <cuda_bf16.h>
#include <cstdint>

// ExpandHarmonics. Output (float32): [hkl 3M | dHKL M | wav M | meta DM*M].
// R4: block-staged scatter -> all global stores are aligned 16B regardless of M%4.

#define MAXN   (1 << 20)
#define BLK    256
#define MAXB   ((MAXN + BLK - 1) / BLK)
#define MAXM   (1 << 23)
#define ROWS_PB 64
#define MAXDM   64

__device__ int           g_rowoff[MAXN];
__device__ unsigned char g_cnt[MAXN];
__device__ int           g_blocksum[MAXB + 1];
__device__ int           g_pack[MAXM];       // (src_idx << 8) | harmonic_n
__device__ unsigned int  g_hkl0[MAXN];       // h0 | k0<<8 | l0<<16
__device__ float         g_d0[MAXN];         // dHKL * g
__device__ float         g_w0[MAXN];         // wavelength * g

__device__ __forceinline__ int gcd2(int a, int b) {
    while (b) { int t = a % b; a = b; b = t; }
    return a;
}

// ---- Pass 1: per-row count + precompute + in-block scan ----
__global__ __launch_bounds__(BLK)
void k_count(const int* __restrict__ hkl, const float* __restrict__ dHKL,
             const float* __restrict__ wav, const float* __restrict__ dmin, int N) {
    __shared__ int s[BLK];
    int i = blockIdx.x * BLK + threadIdx.x;
    int cnt = 0;
    if (i < N) {
        int h = hkl[3 * i], k = hkl[3 * i + 1], l = hkl[3 * i + 2];
        int g = gcd2(gcd2(h, k), l);
        float fg = (float)g;
        float d0 = dHKL[i] * fg;
        cnt = (int)floorf(d0 / dmin[0]);
        g_hkl0[i] = (unsigned)(h / g) | ((unsigned)(k / g) << 8) | ((unsigned)(l / g) << 16);
        g_d0[i] = d0;
        g_w0[i] = wav[i] * fg;
    }
    s[threadIdx.x] = cnt;
    __syncthreads();
    #pragma unroll
    for (int off = 1; off < BLK; off <<= 1) {
        int t = (threadIdx.x >= off) ? s[threadIdx.x - off] : 0;
        __syncthreads();
        s[threadIdx.x] += t;
        __syncthreads();
    }
    if (i < N) {
        g_rowoff[i] = s[threadIdx.x] - cnt;
        g_cnt[i]    = (unsigned char)cnt;
    }
    if (threadIdx.x == 0) g_blocksum[blockIdx.x] = s[BLK - 1];
}

// ---- Pass 2: single-block exclusive scan of block sums ----
__global__ __launch_bounds__(1024)
void k_scan_blocks(int B) {
    __shared__ int s[1024];
    int tid = threadIdx.x;
    int ipt = (B + 1023) / 1024;
    int local[8];
    int start = tid * ipt;
    int sum = 0;
    for (int j = 0; j < ipt; j++) {
        int idx = start + j;
        int v = (idx < B) ? g_blocksum[idx] : 0;
        local[j] = sum;
        sum += v;
    }
    s[tid] = sum;
    __syncthreads();
    #pragma unroll
    for (int off = 1; off < 1024; off <<= 1) {
        int t = (tid >= off) ? s[tid - off] : 0;
        __syncthreads();
        s[tid] += t;
        __syncthreads();
    }
    int base = s[tid] - sum;
    for (int j = 0; j < ipt; j++) {
        int idx = start + j;
        if (idx < B) g_blocksum[idx] = base + local[j];
    }
    if (tid == 1023) g_blocksum[B] = s[1023];
}

// ---- Pass 3: per-output-row (idx, n) pack ----
__global__ __launch_bounds__(BLK)
void k_pack(int N) {
    int i = blockIdx.x * BLK + threadIdx.x;
    if (i >= N) return;
    int off = g_rowoff[i] + g_blocksum[blockIdx.x];
    int cnt = g_cnt[i];
    int tag = i << 8;
    for (int n = 1; n <= cnt; n++)
        g_pack[off + n - 1] = tag | n;
}

// ---- Fused block-staged scatter: 64 output rows per 256-thread block ----
__global__ __launch_bounds__(256)
void k_scatter2(const float* __restrict__ meta, float* __restrict__ out, int M, int DM) {
    __shared__ float s_meta[ROWS_PB * MAXDM];
    __shared__ int   s_pack[ROWS_PB];

    int m0 = blockIdx.x * ROWS_PB;
    int t  = threadIdx.x;
    int nrows = M - m0; if (nrows > ROWS_PB) nrows = ROWS_PB;

    // Phase 1: load pack + scalar outputs (one thread per row)
    if (t < nrows) {
        int m = m0 + t;
        int p = g_pack[m];
        s_pack[t] = p;
        int idx = p >> 8;
        int n   = p & 255;
        unsigned hp = g_hkl0[idx];
        float fn = (float)n;
        out[3 * m + 0] = (float)((int)(hp & 255u) * n);
        out[3 * m + 1] = (float)((int)((hp >> 8) & 255u) * n);
        out[3 * m + 2] = (float)((int)(hp >> 16) * n);
        out[3 * M + m] = g_d0[idx] / fn;
        out[4 * M + m] = g_w0[idx] / fn;
    }
    __syncthreads();

    // Phase 2: gather meta rows into smem (aligned float4 loads from src)
    int DM4  = DM >> 2;                 // float4s per row (8 for DM=32)
    int warp = t >> 5, lane = t & 31;
    int rpw  = 32 / DM4;                // rows per warp per pass
    int rr   = (rpw > 0) ? lane / DM4 : 0;
    int cc   = lane % DM4;
    if (rr < rpw) {
        for (int r = warp * rpw + rr; r < nrows; r += 8 * rpw) {
            int idx = s_pack[r] >> 8;
            float4 v = ((const float4*)(meta + (size_t)idx * DM))[cc];
            ((float4*)s_meta)[r * DM4 + cc] = v;
        }
    }
    __syncthreads();

    // Phase 3: contiguous dst span [gbase, gbase+nrows*DM) with 16B-aligned stores
    size_t gbase = (size_t)5 * M + (size_t)m0 * DM;
    int total = nrows * DM;             // multiple of 4 (DM%4==0)
    int sh = (int)(gbase & 3);          // constant global misalignment in floats
    float* dstf = out + gbase;
    if (sh == 0) {
        float4* dst = (float4*)dstf;
        const float4* s4 = (const float4*)s_meta;
        int nv = total >> 2;
        for (int e = t; e < nv; e += 256) dst[e] = s4[e];
    } else {
        int lead = 4 - sh;              // scalar floats before first aligned 16B slot
        int nv = (total - lead) >> 2;
        for (int e = t; e < nv; e += 256) {
            int o = lead + 4 * e;       // gbase+o is 16B aligned
            float4 v = make_float4(s_meta[o], s_meta[o+1], s_meta[o+2], s_meta[o+3]);
            *(float4*)(dstf + o) = v;
        }
        if (t < lead) dstf[t] = s_meta[t];
        int tr = (total - lead) & 3;
        if (t >= 4 && t < 4 + tr) {
            int o = lead + 4 * nv + (t - 4);
            dstf[o] = s_meta[o];
        }
    }
}

// ---- Fallback (DM not multiple of 4 or too large): R2-style kernels ----
__global__ __launch_bounds__(256)
void k_scalar_fb(float* __restrict__ out, int M) {
    int m = blockIdx.x * 256 + threadIdx.x;
    if (m >= M) return;
    int pack = g_pack[m];
    int idx = pack >> 8;
    int n   = pack & 255;
    unsigned hp = g_hkl0[idx];
    float fn = (float)n;
    out[3 * m + 0] = (float)((int)(hp & 255u) * n);
    out[3 * m + 1] = (float)((int)((hp >> 8) & 255u) * n);
    out[3 * m + 2] = (float)((int)(hp >> 16) * n);
    out[3 * M + m] = g_d0[idx] / fn;
    out[4 * M + m] = g_w0[idx] / fn;
}

__global__ __launch_bounds__(256)
void k_meta_fb(const float* __restrict__ meta, float* __restrict__ out, int M, int DM) {
    int gw   = (blockIdx.x * 256 + threadIdx.x) >> 5;
    int lane = threadIdx.x & 31;
    int r = lane >> 3;
    int c = lane & 7;
    int m = gw * 4 + r;
    if (m >= M) return;
    int idx = g_pack[m] >> 8;
    const float* src = meta + (size_t)idx * DM;
    float*       dst = out + (size_t)5 * M + (size_t)m * DM;
    for (int e = c; e < DM; e += 8)
        dst[e] = src[e];
}

extern "C" void kernel_launch(void* const* d_in, const int* in_sizes, int n_in,
                              void* d_out, int out_size) {
    const int*   hkl  = (const int*)  d_in[0];
    const float* dHKL = (const float*)d_in[1];
    const float* wav  = (const float*)d_in[2];
    const float* meta = (const float*)d_in[3];
    const float* dmin = (const float*)d_in[4];

    int N  = in_sizes[1];
    int DM = in_sizes[3] / N;
    int M  = out_size / (5 + DM);

    int B = (N + BLK - 1) / BLK;

    k_count<<<B, BLK>>>(hkl, dHKL, wav, dmin, N);
    k_scan_blocks<<<1, 1024>>>(B);
    k_pack<<<B, BLK>>>(N);

    if ((DM & 3) == 0 && DM <= MAXDM) {
        int grid = (M + ROWS_PB - 1) / ROWS_PB;
        k_scatter2<<<grid, 256>>>(meta, (float*)d_out, M, DM);
    } else {
        k_scalar_fb<<<(M + 255) / 256, 256>>>((float*)d_out, M);
        int rowsPerBlock = 8 * 4;
        k_meta_fb<<<(M + rowsPerBlock - 1) / rowsPerBlock, 256>>>(meta, (float*)d_out, M, DM);
    }
}